// round 3
// baseline (speedup 1.0000x reference)
#include <cuda_runtime.h>

#define T_LEN 1024
#define S_LEN 1024
#define BSZ   4
#define EMB   1024
#define NH    16
#define HD    64
#define MTOK  (T_LEN*BSZ)   // 4096 tokens

// ---------------------------------------------------------------------------
// Scratch (static __device__ arrays: allocation-free, graph-safe)
// ---------------------------------------------------------------------------
__device__ float g_q [(size_t)MTOK * EMB];                 //  16 MB  q (scaled, +bias)
__device__ float g_kv[(size_t)MTOK * 2 * EMB];             //  32 MB  k|v
__device__ float g_p [(size_t)BSZ * NH * T_LEN * S_LEN];   // 256 MB  scores -> probs (in place)
__device__ float g_ao[(size_t)MTOK * EMB];                 //  16 MB  attn output (t,b,e)

// ---------------------------------------------------------------------------
// Fast exp: FMA polynomial (avoids MUFU throughput wall; rel err ~2e-7)
// Valid for x <= 0 (inputs are score - rowmax).
// ---------------------------------------------------------------------------
__device__ __forceinline__ float fast_exp(float x) {
    float t = x * 1.4426950408889634f;          // x * log2(e)
    t = fmaxf(t, -126.0f);                      // avoid denormal scale
    int   i = __float2int_rn(t);
    float f = t - (float)i;                     // f in [-0.5, 0.5]
    float p = 1.5403530e-4f;                    // Taylor of 2^f = e^{f ln2}
    p = fmaf(p, f, 1.3333558e-3f);
    p = fmaf(p, f, 9.6181291e-3f);
    p = fmaf(p, f, 5.5504109e-2f);
    p = fmaf(p, f, 2.4022651e-1f);
    p = fmaf(p, f, 6.9314718e-1f);
    p = fmaf(p, f, 1.0f);
    return p * __int_as_float((i + 127) << 23);
}

// ---------------------------------------------------------------------------
// Generic strided / batched fp32 SGEMM.
//   C[m,n] = sum_k A[m,k] * B[n,k]   (BKM = true,  "NT": B row-major over n, k contig)
//   C[m,n] = sum_k A[m,k] * B[k,n]   (BKM = false, "NN": B row-major over k, n contig)
// batch z: b = z / nH, h = z % nH; pointer offsets aB*b + aH*h etc.
// Epilogue: C = (acc + bias[n]) * scale   (bias may be null)
// All dims assumed multiples of the tile sizes (true for this problem).
// ---------------------------------------------------------------------------
template<int BM, int BN, int BK, int TM, int TN, bool BKM>
__global__ __launch_bounds__((BM/TM)*(BN/TN), 2)
void sgemm(const float* __restrict__ A, const float* __restrict__ Bm,
           float* __restrict__ C,
           int M, int N, int K, int lda, int ldb, int ldc,
           long long aB, long long aH, long long bB, long long bH,
           long long cB, long long cH, int nH,
           const float* __restrict__ bias, float scale)
{
    constexpr int THREADS = (BM/TM)*(BN/TN);
    constexpr int KV4 = BK/4;

    const int z  = blockIdx.z;
    const int bb = z / nH;
    const int hh = z - bb * nH;
    A  += aB*bb + aH*hh;
    Bm += bB*bb + bH*hh;
    C  += cB*bb + cH*hh;

    __shared__ float As[BK][BM + 4];
    __shared__ float Bs[BK][BN + 4];

    const int tid  = threadIdx.x;
    const int m0   = blockIdx.y * BM;
    const int n0   = blockIdx.x * BN;
    const int tRow = (tid / (BN/TN)) * TM;
    const int tCol = (tid % (BN/TN)) * TN;

    float acc[TM][TN];
#pragma unroll
    for (int i = 0; i < TM; i++)
#pragma unroll
        for (int j = 0; j < TN; j++) acc[i][j] = 0.0f;

    for (int kt = 0; kt < K; kt += BK) {
        // ---- load A tile (m-major, k contiguous) -> As[k][m] ----
#pragma unroll
        for (int ld = 0; ld < (BM*BK)/(THREADS*4); ld++) {
            int e  = tid + ld*THREADS;
            int r  = e / KV4;
            int kc = e - r*KV4;
            float4 v = *(const float4*)(A + (long long)(m0 + r)*lda + kt + kc*4);
            As[kc*4+0][r] = v.x; As[kc*4+1][r] = v.y;
            As[kc*4+2][r] = v.z; As[kc*4+3][r] = v.w;
        }
        // ---- load B tile ----
        if constexpr (BKM) {
#pragma unroll
            for (int ld = 0; ld < (BN*BK)/(THREADS*4); ld++) {
                int e  = tid + ld*THREADS;
                int r  = e / KV4;
                int kc = e - r*KV4;
                float4 v = *(const float4*)(Bm + (long long)(n0 + r)*ldb + kt + kc*4);
                Bs[kc*4+0][r] = v.x; Bs[kc*4+1][r] = v.y;
                Bs[kc*4+2][r] = v.z; Bs[kc*4+3][r] = v.w;
            }
        } else {
#pragma unroll
            for (int ld = 0; ld < (BK*BN)/(THREADS*4); ld++) {
                int e  = tid + ld*THREADS;
                int r  = e / (BN/4);
                int nc = e - r*(BN/4);
                float4 v = *(const float4*)(Bm + (long long)(kt + r)*ldb + n0 + nc*4);
                *(float4*)&Bs[r][nc*4] = v;
            }
        }
        __syncthreads();

#pragma unroll
        for (int kk = 0; kk < BK; kk++) {
            float a[TM], b[TN];
#pragma unroll
            for (int i = 0; i < TM; i++) a[i] = As[kk][tRow + i];
#pragma unroll
            for (int j = 0; j < TN; j++) b[j] = Bs[kk][tCol + j];
#pragma unroll
            for (int i = 0; i < TM; i++)
#pragma unroll
                for (int j = 0; j < TN; j++)
                    acc[i][j] = fmaf(a[i], b[j], acc[i][j]);
        }
        __syncthreads();
    }

    // ---- epilogue: bias + scale, vectorized stores ----
#pragma unroll
    for (int i = 0; i < TM; i++) {
#pragma unroll
        for (int j4 = 0; j4 < TN; j4 += 4) {
            int n = n0 + tCol + j4;
            float4 bv = bias ? *(const float4*)(bias + n)
                             : make_float4(0.f, 0.f, 0.f, 0.f);
            float4 o;
            o.x = (acc[i][j4+0] + bv.x) * scale;
            o.y = (acc[i][j4+1] + bv.y) * scale;
            o.z = (acc[i][j4+2] + bv.z) * scale;
            o.w = (acc[i][j4+3] + bv.w) * scale;
            *(float4*)(C + (long long)(m0 + tRow + i)*ldc + n) = o;
        }
    }
}

// ---------------------------------------------------------------------------
// Fused softmax * mask + avg-over-heads.
// One block per (t, b). 256 threads; thread owns 4 consecutive s indices.
// Probabilities written in place over the scores buffer. avg in registers
// (no atomics -> deterministic).
// ---------------------------------------------------------------------------
__global__ __launch_bounds__(256)
void softmax_kernel(float* __restrict__ P,
                    const float* __restrict__ mask,
                    float* __restrict__ avg)
{
    const int t   = blockIdx.x;
    const int b   = blockIdx.y;
    const int tid = threadIdx.x;
    const int s0  = tid * 4;
    __shared__ float red[8];

    const float4 mk = *(const float4*)(mask + ((long long)b*T_LEN + t)*S_LEN + s0);
    float avx = 0.f, avy = 0.f, avz = 0.f, avw = 0.f;

    for (int h = 0; h < NH; ++h) {
        float* row = P + ((long long)(b*NH + h)*T_LEN + t)*S_LEN;
        float4 r = *(const float4*)(row + s0);

        // --- block max ---
        float mx = fmaxf(fmaxf(r.x, r.y), fmaxf(r.z, r.w));
#pragma unroll
        for (int o = 16; o; o >>= 1) mx = fmaxf(mx, __shfl_xor_sync(0xffffffffu, mx, o));
        if ((tid & 31) == 0) red[tid >> 5] = mx;
        __syncthreads();
        mx = red[0];
#pragma unroll
        for (int w = 1; w < 8; w++) mx = fmaxf(mx, red[w]);
        __syncthreads();

        // --- exp + block sum ---
        float4 e;
        e.x = fast_exp(r.x - mx); e.y = fast_exp(r.y - mx);
        e.z = fast_exp(r.z - mx); e.w = fast_exp(r.w - mx);
        float sm = (e.x + e.y) + (e.z + e.w);
#pragma unroll
        for (int o = 16; o; o >>= 1) sm += __shfl_xor_sync(0xffffffffu, sm, o);
        if ((tid & 31) == 0) red[tid >> 5] = sm;
        __syncthreads();
        sm = ((red[0] + red[1]) + (red[2] + red[3]))
           + ((red[4] + red[5]) + (red[6] + red[7]));
        __syncthreads();

        // --- normalize, mask, write back, accumulate avg ---
        float inv = 1.0f / sm;
        float4 pv;
        pv.x = e.x * inv * mk.x; pv.y = e.y * inv * mk.y;
        pv.z = e.z * inv * mk.z; pv.w = e.w * inv * mk.w;
        *(float4*)(row + s0) = pv;
        avx += pv.x; avy += pv.y; avz += pv.z; avw += pv.w;
    }

    const float k = 1.0f / (float)NH;
    float4 o = make_float4(avx*k, avy*k, avz*k, avw*k);
    *(float4*)(avg + ((long long)b*T_LEN + t)*S_LEN + s0) = o;
}

// ---------------------------------------------------------------------------
// Launch orchestration.
// Inputs (metadata order): query, key, hard_attention, in_proj_weight,
//                          in_proj_bias, out_proj_weight, out_proj_bias
// Output: out (T,B,E) fp32 followed by avg_weights (B,T,S) fp32.
// ---------------------------------------------------------------------------
extern "C" void kernel_launch(void* const* d_in, const int* in_sizes, int n_in,
                              void* d_out, int out_size)
{
    (void)in_sizes; (void)n_in; (void)out_size;
    const float* query = (const float*)d_in[0];
    const float* key   = (const float*)d_in[1];
    const float* mask  = (const float*)d_in[2];
    const float* wIn   = (const float*)d_in[3];
    const float* bIn   = (const float*)d_in[4];
    const float* wOut  = (const float*)d_in[5];
    const float* bOut  = (const float*)d_in[6];

    float* out = (float*)d_out;                           // (t,b,e)
    float* avg = out + (size_t)T_LEN * BSZ * EMB;         // (b,t,s)

    float *q, *kv, *p, *ao;
    cudaGetSymbolAddress((void**)&q,  g_q);
    cudaGetSymbolAddress((void**)&kv, g_kv);
    cudaGetSymbolAddress((void**)&p,  g_p);
    cudaGetSymbolAddress((void**)&ao, g_ao);

    const float scaling = 0.125f;   // hd^-0.5 = 64^-0.5

    // 1) Q = (query @ Wq^T + bq) * scaling        [4096 x 1024, K=1024]
    sgemm<128,128,16,8,8,true><<<dim3(EMB/128, MTOK/128, 1), 256>>>(
        query, wIn, q, MTOK, EMB, EMB, EMB, EMB, EMB,
        0,0,0,0,0,0, 1, bIn, scaling);

    // 2) KV = key @ Wkv^T + bkv                   [4096 x 2048, K=1024]
    sgemm<128,128,16,8,8,true><<<dim3(2*EMB/128, MTOK/128, 1), 256>>>(
        key, wIn + (size_t)EMB*EMB, kv, MTOK, 2*EMB, EMB, EMB, EMB, 2*EMB,
        0,0,0,0,0,0, 1, bIn + EMB, 1.0f);

    // 3) scores[b,h] = Q_bh @ K_bh^T              [1024 x 1024, K=64] x 64 batches
    sgemm<128,128,16,8,8,true><<<dim3(S_LEN/128, T_LEN/128, BSZ*NH), 256>>>(
        q, kv, p, T_LEN, S_LEN, HD,
        BSZ*EMB /*lda*/, BSZ*2*EMB /*ldb*/, S_LEN /*ldc*/,
        (long long)EMB, (long long)HD,                 // A offsets: b*E + h*64
        (long long)2*EMB, (long long)HD,               // B offsets: b*2E + h*64
        (long long)NH*T_LEN*S_LEN, (long long)T_LEN*S_LEN,  // C offsets
        NH, nullptr, 1.0f);

    // 4) softmax * mask, avg over heads (in place on p, avg -> d_out tail)
    softmax_kernel<<<dim3(T_LEN, BSZ), 256>>>(p, mask, avg);

    // 5) attn_out[b,h] = P_bh @ V_bh              [1024 x 64, K=1024] x 64 batches
    sgemm<128,64,16,8,4,false><<<dim3(1, T_LEN/128, BSZ*NH), 256>>>(
        p, kv + EMB, ao, T_LEN, HD, S_LEN,
        S_LEN /*lda*/, BSZ*2*EMB /*ldb*/, BSZ*EMB /*ldc*/,
        (long long)NH*T_LEN*S_LEN, (long long)T_LEN*S_LEN, // A offsets
        (long long)2*EMB, (long long)HD,                   // B offsets (v half)
        (long long)EMB, (long long)HD,                     // C offsets: b*E + h*64
        NH, nullptr, 1.0f);

    // 6) out = attn_out @ Wout^T + bout           [4096 x 1024, K=1024]
    sgemm<128,128,16,8,8,true><<<dim3(EMB/128, MTOK/128, 1), 256>>>(
        ao, wOut, out, MTOK, EMB, EMB, EMB, EMB, EMB,
        0,0,0,0,0,0, 1, bOut, 1.0f);
}